// round 3
// baseline (speedup 1.0000x reference)
#include <cuda_runtime.h>
#include <cstdint>

#define NMAX 50000
#define EMAX 1600000
#define D 128
#define WPAD 132  // 128 + 4: keeps 16B alignment for float4 LDS, rotates banks

// Scratch (device-global: no runtime allocation allowed)
__device__ int   g_is64;
__device__ int   g_src[EMAX];
__device__ int   g_dst[EMAX];
__device__ float g_deg[NMAX];
__device__ float g_dinv[NMAX];
__device__ float g_agg[(size_t)NMAX * D];

// ---------------------------------------------------------------------------
// Phase -1: detect edge dtype. If data is int64 (values < 2^31, nonneg),
// every odd 32-bit word is zero. For int32 data, that is (statistically)
// never true across 1024 samples. Deterministic given the input.
// ---------------------------------------------------------------------------
__global__ void detect_kernel(const int* __restrict__ edge32, int nwords) {
    __shared__ int any_nonzero;
    if (threadIdx.x == 0) any_nonzero = 0;
    __syncthreads();
    // sample odd words across first min(nwords, 2048) words
    for (int i = 1 + 2 * threadIdx.x; i < 2048 && i < nwords; i += 2 * blockDim.x) {
        if (edge32[i] != 0) any_nonzero = 1;
    }
    __syncthreads();
    if (threadIdx.x == 0) g_is64 = any_nonzero ? 0 : 1;
}

// ---------------------------------------------------------------------------
// Phase 0: init — agg = 0, deg = 1 (self-loop pre-counted)
// ---------------------------------------------------------------------------
__global__ void init_kernel(int n) {
    size_t total4 = (size_t)n * D / 4;
    float4 z = make_float4(0.f, 0.f, 0.f, 0.f);
    for (size_t i = (size_t)blockIdx.x * blockDim.x + threadIdx.x; i < total4;
         i += (size_t)gridDim.x * blockDim.x)
        reinterpret_cast<float4*>(g_agg)[i] = z;
    for (int i = blockIdx.x * blockDim.x + threadIdx.x; i < n;
         i += gridDim.x * blockDim.x)
        g_deg[i] = 1.0f;
}

// ---------------------------------------------------------------------------
// Phase 0b: convert edges to int32 arrays (dtype-agnostic)
// ---------------------------------------------------------------------------
__global__ void convert_kernel(const void* __restrict__ edge, int E) {
    int is64 = g_is64;
    for (int i = blockIdx.x * blockDim.x + threadIdx.x; i < E;
         i += gridDim.x * blockDim.x) {
        int s, d;
        if (is64) {
            const long long* e = (const long long*)edge;
            s = (int)e[i];
            d = (int)e[E + i];
        } else {
            const int* e = (const int*)edge;
            s = e[i];
            d = e[E + i];
        }
        g_src[i] = s;
        g_dst[i] = d;
    }
}

// ---------------------------------------------------------------------------
// Phase 1: in-degree (dst side), float so we can rsqrt directly
// ---------------------------------------------------------------------------
__global__ void degree_kernel(int E) {
    for (int i = blockIdx.x * blockDim.x + threadIdx.x; i < E;
         i += gridDim.x * blockDim.x) {
        atomicAdd(&g_deg[g_dst[i]], 1.0f);  // result unused -> REDG
    }
}

// ---------------------------------------------------------------------------
// Phase 2: dinv = rsqrt(deg)  (deg >= 1 always: self-loops)
// ---------------------------------------------------------------------------
__global__ void dinv_kernel(int n) {
    for (int i = blockIdx.x * blockDim.x + threadIdx.x; i < n;
         i += gridDim.x * blockDim.x)
        g_dinv[i] = rsqrtf(g_deg[i]);
}

// ---------------------------------------------------------------------------
// Phase 3: edge scatter. One warp per edge; lane l covers features 4l..4l+3.
// Gather x[src] as float4 (coalesced), scale by dinv[src]*dinv[dst],
// scalar atomicAdd (REDG) into agg[dst].
// ---------------------------------------------------------------------------
__global__ void scatter_kernel(const float4* __restrict__ x4, int E) {
    int warp = (int)((blockIdx.x * (size_t)blockDim.x + threadIdx.x) >> 5);
    int lane = threadIdx.x & 31;
    if (warp >= E) return;
    int s = g_src[warp];
    int d = g_dst[warp];
    float norm = g_dinv[s] * g_dinv[d];
    float4 v = __ldg(&x4[(size_t)s * (D / 4) + lane]);
    float* p = g_agg + (size_t)d * D + lane * 4;
    atomicAdd(p + 0, v.x * norm);
    atomicAdd(p + 1, v.y * norm);
    atomicAdd(p + 2, v.z * norm);
    atomicAdd(p + 3, v.w * norm);
}

// ---------------------------------------------------------------------------
// Phase 4: h = (agg + selfloop) @ W^T + b ; out = x + relu(h)
// Block = 32 nodes. Wsm[k][f] (transposed, padded). 128 threads:
//   warp ng (0..3) owns nodes node0 + ng*8 .. +8
//   lane (0..31) owns features 4*lane .. 4*lane+3
// 8x4 register accumulators; Asm reads are warp-broadcast, Wsm reads LDS.128.
// ---------------------------------------------------------------------------
__global__ __launch_bounds__(128) void gemm_relu_kernel(
    const float* __restrict__ x, const float* __restrict__ W,
    const float* __restrict__ b, float* __restrict__ out, int n) {
    __shared__ float Wsm[D * WPAD];
    __shared__ float Asm[32 * D];

    int tid = threadIdx.x;
    // Load + transpose W: Wsm[k*WPAD + f] = W[f*128 + k]
    for (int i = tid; i < D * D; i += 128) {
        int f = i >> 7;
        int k = i & 127;
        Wsm[k * WPAD + f] = W[i];
    }

    int node0 = blockIdx.x * 32;
    // Load agg tile, folding in the self-loop term x[i] * dinv[i]^2
    for (int i = tid; i < 32 * D; i += 128) {
        int nl = i >> 7;
        int k = i & 127;
        int node = node0 + nl;
        float v = 0.f;
        if (node < n) {
            float di = g_dinv[node];
            v = g_agg[(size_t)node * D + k] + x[(size_t)node * D + k] * di * di;
        }
        Asm[i] = v;
    }
    __syncthreads();

    int f4 = (tid & 31) * 4;
    int ng = tid >> 5;  // warp id: node subgroup
    float acc[8][4];
#pragma unroll
    for (int j = 0; j < 8; j++)
#pragma unroll
        for (int c = 0; c < 4; c++) acc[j][c] = 0.f;

#pragma unroll 4
    for (int k = 0; k < D; k++) {
        float4 w = *reinterpret_cast<const float4*>(&Wsm[k * WPAD + f4]);
#pragma unroll
        for (int j = 0; j < 8; j++) {
            float a = Asm[(ng * 8 + j) * D + k];  // warp-broadcast
            acc[j][0] += a * w.x;
            acc[j][1] += a * w.y;
            acc[j][2] += a * w.z;
            acc[j][3] += a * w.w;
        }
    }

    float4 bb = *reinterpret_cast<const float4*>(&b[f4]);
#pragma unroll
    for (int j = 0; j < 8; j++) {
        int node = node0 + ng * 8 + j;
        if (node >= n) continue;
        float4 xv = *reinterpret_cast<const float4*>(&x[(size_t)node * D + f4]);
        float4 o;
        o.x = xv.x + fmaxf(acc[j][0] + bb.x, 0.f);
        o.y = xv.y + fmaxf(acc[j][1] + bb.y, 0.f);
        o.z = xv.z + fmaxf(acc[j][2] + bb.z, 0.f);
        o.w = xv.w + fmaxf(acc[j][3] + bb.w, 0.f);
        *reinterpret_cast<float4*>(&out[(size_t)node * D + f4]) = o;
    }
}

// ---------------------------------------------------------------------------
extern "C" void kernel_launch(void* const* d_in, const int* in_sizes, int n_in,
                              void* d_out, int out_size) {
    const float* x = (const float*)d_in[0];
    const void* edge = d_in[1];
    const float* W = (const float*)d_in[2];
    const float* b = (const float*)d_in[3];
    float* out = (float*)d_out;

    int n = in_sizes[0] / D;  // 50000
    int E = in_sizes[1] / 2;  // 1,600,000
    if (E > EMAX) E = EMAX;

    detect_kernel<<<1, 256>>>((const int*)edge, in_sizes[1]);
    init_kernel<<<2048, 256>>>(n);
    convert_kernel<<<(E + 255) / 256, 256>>>(edge, E);
    degree_kernel<<<(E + 255) / 256, 256>>>(E);
    dinv_kernel<<<(n + 255) / 256, 256>>>(n);
    {
        // 1 warp per edge, 8 warps per block
        int blocks = (E + 7) / 8;
        scatter_kernel<<<blocks, 256>>>((const float4*)x, E);
    }
    gemm_relu_kernel<<<(n + 31) / 32, 128>>>(x, W, b, out, n);
}

// round 4
// speedup vs baseline: 1.9851x; 1.9851x over previous
#include <cuda_runtime.h>
#include <cstdint>

#define NMAX 50000
#define EMAX 1600000
#define D 128
#define WPAD 132
#define SCAN_T 1024

// Scratch (device globals: no runtime allocation allowed)
__device__ int   g_is64;
__device__ int   g_src[EMAX];
__device__ int   g_dst[EMAX];
__device__ int   g_csr_src[EMAX];
__device__ int   g_degi[NMAX];
__device__ int   g_row_start[NMAX + 1];
__device__ int   g_cursor[NMAX];
__device__ float g_dinv[NMAX];
__device__ float g_agg[(size_t)NMAX * D];

// ---------------------------------------------------------------------------
// Phase -1: detect edge dtype (int64 vs int32). Values < 2^31 -> odd words 0.
// ---------------------------------------------------------------------------
__global__ void detect_kernel(const int* __restrict__ edge32, int nwords) {
    __shared__ int any_nonzero;
    if (threadIdx.x == 0) any_nonzero = 0;
    __syncthreads();
    for (int i = 1 + 2 * threadIdx.x; i < 2048 && i < nwords; i += 2 * blockDim.x)
        if (edge32[i] != 0) any_nonzero = 1;
    __syncthreads();
    if (threadIdx.x == 0) g_is64 = any_nonzero ? 0 : 1;
}

// ---------------------------------------------------------------------------
// Phase 0: zero degree counters
// ---------------------------------------------------------------------------
__global__ void zero_kernel(int n) {
    for (int i = blockIdx.x * blockDim.x + threadIdx.x; i < n;
         i += gridDim.x * blockDim.x)
        g_degi[i] = 0;
}

// ---------------------------------------------------------------------------
// Phase 1: convert edges to int32 + count in-degrees (fused)
// ---------------------------------------------------------------------------
__global__ void convert_degree_kernel(const void* __restrict__ edge, int E) {
    int is64 = g_is64;
    for (int i = blockIdx.x * blockDim.x + threadIdx.x; i < E;
         i += gridDim.x * blockDim.x) {
        int s, d;
        if (is64) {
            const long long* e = (const long long*)edge;
            s = (int)e[i];
            d = (int)e[E + i];
        } else {
            const int* e = (const int*)edge;
            s = e[i];
            d = e[E + i];
        }
        g_src[i] = s;
        g_dst[i] = d;
        atomicAdd(&g_degi[d], 1);  // no return use -> REDG
    }
}

// ---------------------------------------------------------------------------
// Phase 2: dinv = rsqrt(deg + 1)  (+1 = self-loop)
// ---------------------------------------------------------------------------
__global__ void dinv_kernel(int n) {
    for (int i = blockIdx.x * blockDim.x + threadIdx.x; i < n;
         i += gridDim.x * blockDim.x)
        g_dinv[i] = rsqrtf((float)(g_degi[i] + 1));
}

// ---------------------------------------------------------------------------
// Phase 3: exclusive prefix scan of degrees -> row_start, cursor  (1 block)
// ---------------------------------------------------------------------------
__global__ __launch_bounds__(SCAN_T) void scan_kernel(int n) {
    __shared__ int ssum[SCAN_T];
    int tid = threadIdx.x;
    int chunk = (n + SCAN_T - 1) / SCAN_T;
    int b = tid * chunk;
    int e = min(b + chunk, n);
    int s = 0;
    for (int i = b; i < e; i++) s += g_degi[i];
    ssum[tid] = s;
    __syncthreads();
    // Hillis-Steele inclusive scan over per-thread sums
    for (int off = 1; off < SCAN_T; off <<= 1) {
        int t = (tid >= off) ? ssum[tid - off] : 0;
        __syncthreads();
        ssum[tid] += t;
        __syncthreads();
    }
    int run = ssum[tid] - s;  // exclusive prefix for this thread's chunk
    for (int i = b; i < e; i++) {
        g_row_start[i] = run;
        g_cursor[i] = run;
        run += g_degi[i];
    }
    if (tid == SCAN_T - 1) g_row_start[n] = run;
}

// ---------------------------------------------------------------------------
// Phase 4: counting-sort edges into CSR (src lists grouped by dst)
// ---------------------------------------------------------------------------
__global__ void fill_kernel(int E) {
    for (int i = blockIdx.x * blockDim.x + threadIdx.x; i < E;
         i += gridDim.x * blockDim.x) {
        int d = g_dst[i];
        int pos = atomicAdd(&g_cursor[d], 1);
        g_csr_src[pos] = g_src[i];
    }
}

// ---------------------------------------------------------------------------
// Phase 5: gather-aggregate. One warp per dst node, lane = float4 chunk.
// Pure reads + one STG.128 per chunk: zero feature atomics.
// Unroll-by-4 with separate accumulators -> MLP 4, broken FMA chains.
// ---------------------------------------------------------------------------
__global__ __launch_bounds__(256) void gather_kernel(const float4* __restrict__ x4,
                                                     int n) {
    int node = blockIdx.x * 8 + (threadIdx.x >> 5);
    int lane = threadIdx.x & 31;
    if (node >= n) return;
    int beg = g_row_start[node];
    int end = g_row_start[node + 1];
    float dd = g_dinv[node];

    float4 a0 = make_float4(0.f, 0.f, 0.f, 0.f);
    float4 a1 = make_float4(0.f, 0.f, 0.f, 0.f);
    float4 a2 = make_float4(0.f, 0.f, 0.f, 0.f);
    float4 a3 = make_float4(0.f, 0.f, 0.f, 0.f);

    int e = beg;
    for (; e + 4 <= end; e += 4) {
        int s0 = g_csr_src[e + 0];
        int s1 = g_csr_src[e + 1];
        int s2 = g_csr_src[e + 2];
        int s3 = g_csr_src[e + 3];
        float w0 = g_dinv[s0];
        float w1 = g_dinv[s1];
        float w2 = g_dinv[s2];
        float w3 = g_dinv[s3];
        float4 v0 = __ldg(&x4[(size_t)s0 * 32 + lane]);
        float4 v1 = __ldg(&x4[(size_t)s1 * 32 + lane]);
        float4 v2 = __ldg(&x4[(size_t)s2 * 32 + lane]);
        float4 v3 = __ldg(&x4[(size_t)s3 * 32 + lane]);
        a0.x += v0.x * w0; a0.y += v0.y * w0; a0.z += v0.z * w0; a0.w += v0.w * w0;
        a1.x += v1.x * w1; a1.y += v1.y * w1; a1.z += v1.z * w1; a1.w += v1.w * w1;
        a2.x += v2.x * w2; a2.y += v2.y * w2; a2.z += v2.z * w2; a2.w += v2.w * w2;
        a3.x += v3.x * w3; a3.y += v3.y * w3; a3.z += v3.z * w3; a3.w += v3.w * w3;
    }
    for (; e < end; e++) {
        int s = g_csr_src[e];
        float w = g_dinv[s];
        float4 v = __ldg(&x4[(size_t)s * 32 + lane]);
        a0.x += v.x * w; a0.y += v.y * w; a0.z += v.z * w; a0.w += v.w * w;
    }
    float4 acc;
    acc.x = (a0.x + a1.x) + (a2.x + a3.x);
    acc.y = (a0.y + a1.y) + (a2.y + a3.y);
    acc.z = (a0.z + a1.z) + (a2.z + a3.z);
    acc.w = (a0.w + a1.w) + (a2.w + a3.w);
    // scale whole row by dinv[dst]
    acc.x *= dd; acc.y *= dd; acc.z *= dd; acc.w *= dd;
    reinterpret_cast<float4*>(g_agg)[(size_t)node * 32 + lane] = acc;
}

// ---------------------------------------------------------------------------
// Phase 6: h = (agg + selfloop) @ W^T + b ; out = x + relu(h)
// ---------------------------------------------------------------------------
__global__ __launch_bounds__(128) void gemm_relu_kernel(
    const float* __restrict__ x, const float* __restrict__ W,
    const float* __restrict__ b, float* __restrict__ out, int n) {
    __shared__ float Wsm[D * WPAD];
    __shared__ float Asm[32 * D];

    int tid = threadIdx.x;
    for (int i = tid; i < D * D; i += 128) {
        int f = i >> 7;
        int k = i & 127;
        Wsm[k * WPAD + f] = W[i];
    }

    int node0 = blockIdx.x * 32;
    for (int i = tid; i < 32 * D; i += 128) {
        int nl = i >> 7;
        int k = i & 127;
        int node = node0 + nl;
        float v = 0.f;
        if (node < n) {
            float di = g_dinv[node];
            v = g_agg[(size_t)node * D + k] + x[(size_t)node * D + k] * di * di;
        }
        Asm[i] = v;
    }
    __syncthreads();

    int f4 = (tid & 31) * 4;
    int ng = tid >> 5;
    float acc[8][4];
#pragma unroll
    for (int j = 0; j < 8; j++)
#pragma unroll
        for (int c = 0; c < 4; c++) acc[j][c] = 0.f;

#pragma unroll 4
    for (int k = 0; k < D; k++) {
        float4 w = *reinterpret_cast<const float4*>(&Wsm[k * WPAD + f4]);
#pragma unroll
        for (int j = 0; j < 8; j++) {
            float a = Asm[(ng * 8 + j) * D + k];
            acc[j][0] += a * w.x;
            acc[j][1] += a * w.y;
            acc[j][2] += a * w.z;
            acc[j][3] += a * w.w;
        }
    }

    float4 bb = *reinterpret_cast<const float4*>(&b[f4]);
#pragma unroll
    for (int j = 0; j < 8; j++) {
        int node = node0 + ng * 8 + j;
        if (node >= n) continue;
        float4 xv = *reinterpret_cast<const float4*>(&x[(size_t)node * D + f4]);
        float4 o;
        o.x = xv.x + fmaxf(acc[j][0] + bb.x, 0.f);
        o.y = xv.y + fmaxf(acc[j][1] + bb.y, 0.f);
        o.z = xv.z + fmaxf(acc[j][2] + bb.z, 0.f);
        o.w = xv.w + fmaxf(acc[j][3] + bb.w, 0.f);
        *reinterpret_cast<float4*>(&out[(size_t)node * D + f4]) = o;
    }
}

// ---------------------------------------------------------------------------
extern "C" void kernel_launch(void* const* d_in, const int* in_sizes, int n_in,
                              void* d_out, int out_size) {
    const float* x = (const float*)d_in[0];
    const void* edge = d_in[1];
    const float* W = (const float*)d_in[2];
    const float* b = (const float*)d_in[3];
    float* out = (float*)d_out;

    int n = in_sizes[0] / D;  // 50000
    int E = in_sizes[1] / 2;  // 1,600,000
    if (E > EMAX) E = EMAX;

    detect_kernel<<<1, 256>>>((const int*)edge, in_sizes[1]);
    zero_kernel<<<64, 256>>>(n);
    convert_degree_kernel<<<(E + 255) / 256, 256>>>(edge, E);
    dinv_kernel<<<(n + 255) / 256, 256>>>(n);
    scan_kernel<<<1, SCAN_T>>>(n);
    fill_kernel<<<(E + 255) / 256, 256>>>(E);
    gather_kernel<<<(n + 7) / 8, 256>>>((const float4*)x, n);
    gemm_relu_kernel<<<(n + 31) / 32, 128>>>(x, W, b, out, n);
}

// round 5
// speedup vs baseline: 2.2142x; 1.1154x over previous
#include <cuda_runtime.h>
#include <cstdint>

#define NMAX 50000
#define EMAX 1600000
#define D 128
#define WPAD 132   // W smem row pad (words)
#define APAD 66    // A smem row pad (words): 64 nodes + 2, 264B rows (8B aligned)
#define SCAN_T 1024

typedef unsigned long long ull;

// Scratch (device globals: no runtime allocation allowed)
__device__ int   g_is64;
__device__ int   g_src[EMAX];
__device__ int   g_dst[EMAX];
__device__ int   g_csr_src[EMAX];
__device__ int   g_degi[NMAX];
__device__ int   g_row_start[NMAX + 1];
__device__ int   g_cursor[NMAX];
__device__ float g_dinv[NMAX];
__device__ float g_agg[(size_t)NMAX * D];

#define FMA_F32X2(d, a, b, c) \
    asm("fma.rn.f32x2 %0, %1, %2, %3;" : "=l"(d) : "l"(a), "l"(b), "l"(c))
#define PACK_DUP(out, f) \
    do { unsigned _u = __float_as_uint(f); \
         asm("mov.b64 %0, {%1, %1};" : "=l"(out) : "r"(_u)); } while (0)
#define UNPACK2(lo, hi, in) \
    asm("mov.b64 {%0, %1}, %2;" : "=r"(lo), "=r"(hi) : "l"(in))

// ---------------------------------------------------------------------------
// Phase -1: detect edge dtype (int64 vs int32). Values < 2^31 -> odd words 0.
// ---------------------------------------------------------------------------
__global__ void detect_kernel(const int* __restrict__ edge32, int nwords) {
    __shared__ int any_nonzero;
    if (threadIdx.x == 0) any_nonzero = 0;
    __syncthreads();
    for (int i = 1 + 2 * threadIdx.x; i < 2048 && i < nwords; i += 2 * blockDim.x)
        if (edge32[i] != 0) any_nonzero = 1;
    __syncthreads();
    if (threadIdx.x == 0) g_is64 = any_nonzero ? 0 : 1;
}

__global__ void zero_kernel(int n) {
    for (int i = blockIdx.x * blockDim.x + threadIdx.x; i < n;
         i += gridDim.x * blockDim.x)
        g_degi[i] = 0;
}

// ---------------------------------------------------------------------------
// Phase 1: convert edges to int32 + count in-degrees (fused)
// ---------------------------------------------------------------------------
__global__ void convert_degree_kernel(const void* __restrict__ edge, int E) {
    int is64 = g_is64;
    for (int i = blockIdx.x * blockDim.x + threadIdx.x; i < E;
         i += gridDim.x * blockDim.x) {
        int s, d;
        if (is64) {
            const long long* e = (const long long*)edge;
            s = (int)e[i];
            d = (int)e[E + i];
        } else {
            const int* e = (const int*)edge;
            s = e[i];
            d = e[E + i];
        }
        g_src[i] = s;
        g_dst[i] = d;
        atomicAdd(&g_degi[d], 1);  // no return use -> REDG
    }
}

__global__ void dinv_kernel(int n) {
    for (int i = blockIdx.x * blockDim.x + threadIdx.x; i < n;
         i += gridDim.x * blockDim.x)
        g_dinv[i] = rsqrtf((float)(g_degi[i] + 1));
}

// ---------------------------------------------------------------------------
// Phase 3: exclusive prefix scan of degrees -> row_start, cursor  (1 block)
// ---------------------------------------------------------------------------
__global__ __launch_bounds__(SCAN_T) void scan_kernel(int n) {
    __shared__ int ssum[SCAN_T];
    int tid = threadIdx.x;
    int chunk = (n + SCAN_T - 1) / SCAN_T;
    int b = tid * chunk;
    int e = min(b + chunk, n);
    int s = 0;
    for (int i = b; i < e; i++) s += g_degi[i];
    ssum[tid] = s;
    __syncthreads();
    for (int off = 1; off < SCAN_T; off <<= 1) {
        int t = (tid >= off) ? ssum[tid - off] : 0;
        __syncthreads();
        ssum[tid] += t;
        __syncthreads();
    }
    int run = ssum[tid] - s;
    for (int i = b; i < e; i++) {
        g_row_start[i] = run;
        g_cursor[i] = run;
        run += g_degi[i];
    }
    if (tid == SCAN_T - 1) g_row_start[n] = run;
}

__global__ void fill_kernel(int E) {
    for (int i = blockIdx.x * blockDim.x + threadIdx.x; i < E;
         i += gridDim.x * blockDim.x) {
        int d = g_dst[i];
        int pos = atomicAdd(&g_cursor[d], 1);
        g_csr_src[pos] = g_src[i];
    }
}

// ---------------------------------------------------------------------------
// Phase 5: gather-aggregate. One warp per dst node, lane = float4 chunk.
// Unroll-by-8: 8 outstanding LDG.128 per thread to hide ~250cyc L2 latency.
// ---------------------------------------------------------------------------
__global__ __launch_bounds__(256) void gather_kernel(const float4* __restrict__ x4,
                                                     int n) {
    int node = blockIdx.x * 8 + (threadIdx.x >> 5);
    int lane = threadIdx.x & 31;
    if (node >= n) return;
    int beg = g_row_start[node];
    int end = g_row_start[node + 1];
    float dd = g_dinv[node];

    float4 a[8];
#pragma unroll
    for (int j = 0; j < 8; j++) a[j] = make_float4(0.f, 0.f, 0.f, 0.f);

    int e = beg;
    for (; e + 8 <= end; e += 8) {
        int   s[8];
        float w[8];
        float4 v[8];
#pragma unroll
        for (int j = 0; j < 8; j++) s[j] = g_csr_src[e + j];
#pragma unroll
        for (int j = 0; j < 8; j++) w[j] = g_dinv[s[j]];
#pragma unroll
        for (int j = 0; j < 8; j++) v[j] = __ldg(&x4[(size_t)s[j] * 32 + lane]);
#pragma unroll
        for (int j = 0; j < 8; j++) {
            a[j].x += v[j].x * w[j];
            a[j].y += v[j].y * w[j];
            a[j].z += v[j].z * w[j];
            a[j].w += v[j].w * w[j];
        }
    }
    for (; e < end; e++) {
        int s = g_csr_src[e];
        float w = g_dinv[s];
        float4 v = __ldg(&x4[(size_t)s * 32 + lane]);
        a[0].x += v.x * w; a[0].y += v.y * w; a[0].z += v.z * w; a[0].w += v.w * w;
    }
    float4 acc;
    acc.x = ((a[0].x + a[1].x) + (a[2].x + a[3].x)) + ((a[4].x + a[5].x) + (a[6].x + a[7].x));
    acc.y = ((a[0].y + a[1].y) + (a[2].y + a[3].y)) + ((a[4].y + a[5].y) + (a[6].y + a[7].y));
    acc.z = ((a[0].z + a[1].z) + (a[2].z + a[3].z)) + ((a[4].z + a[5].z) + (a[6].z + a[7].z));
    acc.w = ((a[0].w + a[1].w) + (a[2].w + a[3].w)) + ((a[4].w + a[5].w) + (a[6].w + a[7].w));
    acc.x *= dd; acc.y *= dd; acc.z *= dd; acc.w *= dd;
    reinterpret_cast<float4*>(g_agg)[(size_t)node * 32 + lane] = acc;
}

// ---------------------------------------------------------------------------
// Phase 6: h = (agg + selfloop) @ W^T + b ; out = x + relu(h)
// 64 nodes/block, 256 threads. Warp wg owns nodes node0+8wg..+8 (all lanes
// cover all 8 nodes); lane owns features 4*lane..+4.
// Packed-f32x2 mainloop: node pairs in the packed dim.
//   per k: 4x LDS.64 (node-pair a, warp-broadcast) + 1x LDS.128 (w)
//          + 4 dup-packs + 16 FFMA2  -> FFMA-pipe-bound (~72 TF/s fp32)
// ---------------------------------------------------------------------------
__global__ __launch_bounds__(256) void gemm_relu_kernel(
    const float* __restrict__ x, const float* __restrict__ W,
    const float* __restrict__ b, float* __restrict__ out, int n) {
    __shared__ float Wsm[D * WPAD];   // [k][f]
    __shared__ float Asm[D * APAD];   // [k][node] (transposed tile)

    int tid = threadIdx.x;
    // Load + transpose W: Wsm[k][f] = W[f*128 + k]
    for (int i = tid; i < D * D; i += 256) {
        int f = i >> 7;
        int k = i & 127;
        Wsm[k * WPAD + f] = W[i];
    }

    int node0 = blockIdx.x * 64;
    // Load A tile transposed, folding self-loop term x[i]*dinv[i]^2
    for (int i = tid; i < 64 * D; i += 256) {
        int nl = i >> 7;
        int k = i & 127;
        int node = node0 + nl;
        float v = 0.f;
        if (node < n) {
            float di = g_dinv[node];
            v = g_agg[(size_t)node * D + k] + x[(size_t)node * D + k] * di * di;
        }
        Asm[k * APAD + nl] = v;
    }
    __syncthreads();

    int lane = tid & 31;
    int wg = tid >> 5;       // warp id: node subgroup of 8
    int f4 = lane * 4;

    ull acc[4][4];           // [node_pair][feature], each f32x2 = 2 nodes
#pragma unroll
    for (int p = 0; p < 4; p++)
#pragma unroll
        for (int c = 0; c < 4; c++) acc[p][c] = 0ull;

#pragma unroll 4
    for (int k = 0; k < D; k++) {
        const ull* arow = reinterpret_cast<const ull*>(&Asm[k * APAD + wg * 8]);
        ull A0 = arow[0], A1 = arow[1], A2 = arow[2], A3 = arow[3];
        float4 w = *reinterpret_cast<const float4*>(&Wsm[k * WPAD + f4]);
        ull W0, W1, W2, W3;
        PACK_DUP(W0, w.x);
        PACK_DUP(W1, w.y);
        PACK_DUP(W2, w.z);
        PACK_DUP(W3, w.w);
        FMA_F32X2(acc[0][0], A0, W0, acc[0][0]);
        FMA_F32X2(acc[0][1], A0, W1, acc[0][1]);
        FMA_F32X2(acc[0][2], A0, W2, acc[0][2]);
        FMA_F32X2(acc[0][3], A0, W3, acc[0][3]);
        FMA_F32X2(acc[1][0], A1, W0, acc[1][0]);
        FMA_F32X2(acc[1][1], A1, W1, acc[1][1]);
        FMA_F32X2(acc[1][2], A1, W2, acc[1][2]);
        FMA_F32X2(acc[1][3], A1, W3, acc[1][3]);
        FMA_F32X2(acc[2][0], A2, W0, acc[2][0]);
        FMA_F32X2(acc[2][1], A2, W1, acc[2][1]);
        FMA_F32X2(acc[2][2], A2, W2, acc[2][2]);
        FMA_F32X2(acc[2][3], A2, W3, acc[2][3]);
        FMA_F32X2(acc[3][0], A3, W0, acc[3][0]);
        FMA_F32X2(acc[3][1], A3, W1, acc[3][1]);
        FMA_F32X2(acc[3][2], A3, W2, acc[3][2]);
        FMA_F32X2(acc[3][3], A3, W3, acc[3][3]);
    }

    float4 bb = *reinterpret_cast<const float4*>(&b[f4]);
#pragma unroll
    for (int p = 0; p < 4; p++) {
        unsigned lo0, hi0, lo1, hi1, lo2, hi2, lo3, hi3;
        UNPACK2(lo0, hi0, acc[p][0]);
        UNPACK2(lo1, hi1, acc[p][1]);
        UNPACK2(lo2, hi2, acc[p][2]);
        UNPACK2(lo3, hi3, acc[p][3]);
        int node_e = node0 + wg * 8 + 2 * p;
        if (node_e < n) {
            float4 xv = *reinterpret_cast<const float4*>(&x[(size_t)node_e * D + f4]);
            float4 o;
            o.x = xv.x + fmaxf(__uint_as_float(lo0) + bb.x, 0.f);
            o.y = xv.y + fmaxf(__uint_as_float(lo1) + bb.y, 0.f);
            o.z = xv.z + fmaxf(__uint_as_float(lo2) + bb.z, 0.f);
            o.w = xv.w + fmaxf(__uint_as_float(lo3) + bb.w, 0.f);
            *reinterpret_cast<float4*>(&out[(size_t)node_e * D + f4]) = o;
        }
        int node_o = node_e + 1;
        if (node_o < n) {
            float4 xv = *reinterpret_cast<const float4*>(&x[(size_t)node_o * D + f4]);
            float4 o;
            o.x = xv.x + fmaxf(__uint_as_float(hi0) + bb.x, 0.f);
            o.y = xv.y + fmaxf(__uint_as_float(hi1) + bb.y, 0.f);
            o.z = xv.z + fmaxf(__uint_as_float(hi2) + bb.z, 0.f);
            o.w = xv.w + fmaxf(__uint_as_float(hi3) + bb.w, 0.f);
            *reinterpret_cast<float4*>(&out[(size_t)node_o * D + f4]) = o;
        }
    }
}

// ---------------------------------------------------------------------------
extern "C" void kernel_launch(void* const* d_in, const int* in_sizes, int n_in,
                              void* d_out, int out_size) {
    const float* x = (const float*)d_in[0];
    const void* edge = d_in[1];
    const float* W = (const float*)d_in[2];
    const float* b = (const float*)d_in[3];
    float* out = (float*)d_out;

    int n = in_sizes[0] / D;  // 50000
    int E = in_sizes[1] / 2;  // 1,600,000
    if (E > EMAX) E = EMAX;

    detect_kernel<<<1, 256>>>((const int*)edge, in_sizes[1]);
    zero_kernel<<<64, 256>>>(n);
    convert_degree_kernel<<<(E + 255) / 256, 256>>>(edge, E);
    dinv_kernel<<<(n + 255) / 256, 256>>>(n);
    scan_kernel<<<1, SCAN_T>>>(n);
    fill_kernel<<<(E + 255) / 256, 256>>>(E);
    gather_kernel<<<(n + 7) / 8, 256>>>((const float4*)x, n);
    gemm_relu_kernel<<<(n + 63) / 64, 256>>>(x, W, b, out, n);
}